// round 6
// baseline (speedup 1.0000x reference)
#include <cuda_runtime.h>

// Problem constants (fixed shapes from reference)
#define TSTEPS   512
#define H        32
#define NB       32     // batch tile per CTA
#define NTHREADS 512

// Padded strides (floats)
#define WSTRIDE  68     // weight row [Wih|Whh] = 64 + 4 pad (conflict-free 8-row LDS.128)
#define ISTRIDE  68     // input row per batch: 64 k + 4 pad
#define GSTRIDE  34     // gs row per gate: 32 b + 2 pad

// Dynamic smem layout (float offsets, all 16B aligned)
#define OFF_W0    0                          // 128*68
#define OFF_W1    (OFF_W0 + 128*WSTRIDE)     // 8704
#define OFF_GS    (OFF_W1 + 128*WSTRIDE)     // 17408: 128*34
#define OFF_IN0   (OFF_GS + 128*GSTRIDE)     // 21760: 32*68  layer0 input [x | h0], [b][k]
#define OFF_INB   (OFF_IN0 + 32*ISTRIDE)     // 23936: layer1 input [h0 | h1]
#define OFF_B0    (OFF_INB + 32*ISTRIDE)     // 26112: 128
#define OFF_B1    (OFF_B0 + 128)             // 26240: 128
#define OFF_W1S   (OFF_B1 + 128)             // 26368: 32
#define OFF_B1S   (OFF_W1S + 32)             // 26400: 32
#define OFF_W2S   (OFF_B1S + 32)             // 26432: 64
#define SMEM_FLOATS (OFF_W2S + 64)           // 26496
#define SMEM_BYTES  (SMEM_FLOATS * 4)        // 105984

__device__ __forceinline__ void upk2(unsigned long long v, float& lo, float& hi) {
    asm("mov.b64 {%0,%1}, %2;" : "=f"(lo), "=f"(hi) : "l"(v));
}
__device__ __forceinline__ unsigned long long pck2(float lo, float hi) {
    unsigned long long r;
    asm("mov.b64 %0, {%1,%2};" : "=l"(r) : "f"(lo), "f"(hi));
    return r;
}
// packed fp32x2 FMA: d += a*b elementwise
__device__ __forceinline__ void ffma2(unsigned long long& d, unsigned long long a, unsigned long long b) {
    asm("fma.rn.f32x2 %0, %1, %2, %0;" : "+l"(d) : "l"(a), "l"(b));
}
__device__ __forceinline__ float sigm(float v) {
    float e = __expf(-v);
    return __fdividef(1.0f, 1.0f + e);
}
__device__ __forceinline__ float tanh_(float v) {
    float e = __expf(-2.0f * v);
    return __fdividef(2.0f, 1.0f + e) - 1.0f;
}

// Gate phase: thread computes 4 gate rows {gbase + 8r} x 2 batch {2*bp2, 2*bp2+1}.
// Weights Ws[g][WSTRIDE] (k 0..63), inputs inX[b][ISTRIDE] (k 0..63).
// Accumulate in f32x2 pairs over k (even/odd), bias folded into acc init.
__device__ __forceinline__ void gate_phase(const float* __restrict__ Ws,
                                           const float* __restrict__ inX,
                                           const float* __restrict__ bias,
                                           float* __restrict__ gs,
                                           int gbase, int bp2) {
    unsigned long long acc[4][2];
#pragma unroll
    for (int r = 0; r < 4; r++) {
        float bz = bias[gbase + 8 * r];
        acc[r][0] = pck2(bz, 0.f);
        acc[r][1] = pck2(0.f, 0.f);
    }
    const float* w0  = Ws  + gbase * WSTRIDE;
    const float* ib0 = inX + (2 * bp2) * ISTRIDE;
    const float* ib1 = ib0 + ISTRIDE;
#pragma unroll
    for (int kq = 0; kq < 16; kq++) {
        ulonglong2 i0 = *(const ulonglong2*)(ib0 + 4 * kq);
        ulonglong2 i1 = *(const ulonglong2*)(ib1 + 4 * kq);
#pragma unroll
        for (int r = 0; r < 4; r++) {
            ulonglong2 w = *(const ulonglong2*)(w0 + (8 * r) * WSTRIDE + 4 * kq);
            ffma2(acc[r][0], w.x, i0.x);
            ffma2(acc[r][0], w.y, i0.y);
            ffma2(acc[r][1], w.x, i1.x);
            ffma2(acc[r][1], w.y, i1.y);
        }
    }
#pragma unroll
    for (int r = 0; r < 4; r++) {
        float l0, h0v, l1, h1v;
        upk2(acc[r][0], l0, h0v);
        upk2(acc[r][1], l1, h1v);
        // bias was folded into acc[r][0] only; add to second batch here
        float bz = bias[gbase + 8 * r];
        *(float2*)&gs[(gbase + 8 * r) * GSTRIDE + 2 * bp2] =
            make_float2(l0 + h0v, l1 + h1v + bz);
    }
}

// Update: thread (ug, ub) owns cell states for j = 2*ug, 2*ug+1 at batch ub.
__device__ __forceinline__ void update2(const float* __restrict__ gs,
                                        int ug, int ub,
                                        float& ca, float& cb,
                                        float& ha, float& hb) {
    int j0 = 2 * ug;
    {
        float iv = sigm(gs[(0 * H + j0) * GSTRIDE + ub]);
        float fv = sigm(gs[(1 * H + j0) * GSTRIDE + ub]);
        float gv = tanh_(gs[(2 * H + j0) * GSTRIDE + ub]);
        float ov = sigm(gs[(3 * H + j0) * GSTRIDE + ub]);
        ca = fmaf(fv, ca, iv * gv);
        ha = ov * tanh_(ca);
    }
    {
        int j1 = j0 + 1;
        float iv = sigm(gs[(0 * H + j1) * GSTRIDE + ub]);
        float fv = sigm(gs[(1 * H + j1) * GSTRIDE + ub]);
        float gv = tanh_(gs[(2 * H + j1) * GSTRIDE + ub]);
        float ov = sigm(gs[(3 * H + j1) * GSTRIDE + ub]);
        cb = fmaf(fv, cb, iv * gv);
        hb = ov * tanh_(cb);
    }
}

__global__ void __launch_bounds__(NTHREADS, 1)
lstm_fused_kernel(const float* __restrict__ tensor,
                  const float* __restrict__ w1,   const float* __restrict__ b1,
                  const float* __restrict__ Wih0, const float* __restrict__ Whh0,
                  const float* __restrict__ bih0, const float* __restrict__ bhh0,
                  const float* __restrict__ Wih1, const float* __restrict__ Whh1,
                  const float* __restrict__ bih1, const float* __restrict__ bhh1,
                  const float* __restrict__ w2,   const float* __restrict__ b2,
                  float* __restrict__ out) {
    extern __shared__ float smem[];
    float* W0s   = smem + OFF_W0;
    float* W1s   = smem + OFF_W1;
    float* gs    = smem + OFF_GS;
    float* in0   = smem + OFF_IN0;
    float* inB   = smem + OFF_INB;
    float* bias0 = smem + OFF_B0;
    float* bias1 = smem + OFF_B1;
    float* w1s   = smem + OFF_W1S;
    float* b1s   = smem + OFF_B1S;
    float* w2s   = smem + OFF_W2S;

    const int tid = threadIdx.x;
    // Gate-phase mapping: warp w = (gw: gate block of 32, bw: batch block of 8)
    const int l   = tid & 31;
    const int w   = tid >> 5;
    const int lg  = l & 7;            // gate lane 0..7
    const int lb  = l >> 3;           // batch-pair lane 0..3
    const int gw  = w & 3;
    const int bw  = w >> 2;
    const int gbase = gw * 32 + lg;   // rows gbase + 8r
    const int bp2   = bw * 4 + lb;    // batch pair index (b = 2*bp2, 2*bp2+1)
    // Update-phase mapping
    const int ug = tid >> 5;          // 0..15, owns j = 2ug, 2ug+1
    const int ub = tid & 31;          // batch 0..31

    // ---- Preload weights / biases into SMEM ----
    for (int idx = tid; idx < 128 * 32; idx += NTHREADS) {
        int g = idx >> 5, k = idx & 31;
        W0s[g * WSTRIDE + k]      = Wih0[idx];
        W0s[g * WSTRIDE + 32 + k] = Whh0[idx];
        W1s[g * WSTRIDE + k]      = Wih1[idx];
        W1s[g * WSTRIDE + 32 + k] = Whh1[idx];
    }
    for (int idx = tid; idx < 128; idx += NTHREADS) {
        bias0[idx] = bih0[idx] + bhh0[idx];
        bias1[idx] = bih1[idx] + bhh1[idx];
    }
    if (tid < 32) { w1s[tid] = w1[tid]; b1s[tid] = b1[tid]; }
    if (tid < 64) { w2s[tid] = w2[tid]; }
    __syncthreads();

    const int bg_u = blockIdx.x * NB + ub;
    const float* __restrict__ seq = tensor + (long)bg_u * TSTEPS;

    // ---- Init staging: x(t=0), h0 = h1 = 0 ----
    {
        int j0 = 2 * ug;
        float s  = seq[0];
        float xa = fmaxf(fmaf(s, w1s[j0],     b1s[j0]),     0.f);
        float xb = fmaxf(fmaf(s, w1s[j0 + 1], b1s[j0 + 1]), 0.f);
        *(float2*)&in0[ub * ISTRIDE + j0]      = make_float2(xa, xb);
        *(float2*)&in0[ub * ISTRIDE + 32 + j0] = make_float2(0.f, 0.f);
        *(float2*)&inB[ub * ISTRIDE + j0]      = make_float2(0.f, 0.f);
        *(float2*)&inB[ub * ISTRIDE + 32 + j0] = make_float2(0.f, 0.f);
    }
    float c0a = 0.f, c0b = 0.f, c1a = 0.f, c1b = 0.f;
    __syncthreads();

    for (int t = 0; t < TSTEPS; t++) {
        // ---- Layer 0 gates ----
        gate_phase(W0s, in0, bias0, gs, gbase, bp2);
        __syncthreads();                                   // S1

        // ---- Layer 0 update ----
        {
            float ha, hb;
            update2(gs, ug, ub, c0a, c0b, ha, hb);
            float2 h = make_float2(ha, hb);
            *(float2*)&in0[ub * ISTRIDE + 32 + 2 * ug] = h;  // h0 for next-step layer0
            *(float2*)&inB[ub * ISTRIDE + 2 * ug]      = h;  // h0 into layer1 input
        }
        __syncthreads();                                   // S2

        // ---- Layer 1 gates ----
        gate_phase(W1s, inB, bias1, gs, gbase, bp2);
        __syncthreads();                                   // S3

        // ---- Layer 1 update + next-step x ----
        {
            float ha, hb;
            update2(gs, ug, ub, c1a, c1b, ha, hb);
            *(float2*)&inB[ub * ISTRIDE + 32 + 2 * ug] = make_float2(ha, hb);
            if (t + 1 < TSTEPS) {
                int j0 = 2 * ug;
                float s  = seq[t + 1];
                float xa = fmaxf(fmaf(s, w1s[j0],     b1s[j0]),     0.f);
                float xb = fmaxf(fmaf(s, w1s[j0 + 1], b1s[j0 + 1]), 0.f);
                *(float2*)&in0[ub * ISTRIDE + j0] = make_float2(xa, xb);
            }
        }
        __syncthreads();                                   // S4
    }

    // ---- Head: out[b] = [h0_final ; h1_final] . w2 + b2 ----
    if (tid < 32) {
        int b = tid;
        const unsigned long long* h0p = (const unsigned long long*)(in0 + b * ISTRIDE + 32);
        const unsigned long long* h1p = (const unsigned long long*)(inB + b * ISTRIDE + 32);
        const unsigned long long* wp  = (const unsigned long long*)w2s;
        unsigned long long acc = 0ull;
#pragma unroll
        for (int kp = 0; kp < 16; kp++) ffma2(acc, wp[kp], h0p[kp]);
#pragma unroll
        for (int kp = 0; kp < 16; kp++) ffma2(acc, wp[16 + kp], h1p[kp]);
        float lo, hi;
        upk2(acc, lo, hi);
        out[blockIdx.x * NB + b] = lo + hi + b2[0];
    }
}

extern "C" void kernel_launch(void* const* d_in, const int* in_sizes, int n_in,
                              void* d_out, int out_size) {
    const float* tensor = (const float*)d_in[0];
    const float* w1     = (const float*)d_in[1];
    const float* b1     = (const float*)d_in[2];
    const float* Wih0   = (const float*)d_in[3];
    const float* Whh0   = (const float*)d_in[4];
    const float* bih0   = (const float*)d_in[5];
    const float* bhh0   = (const float*)d_in[6];
    const float* Wih1   = (const float*)d_in[7];
    const float* Whh1   = (const float*)d_in[8];
    const float* bih1   = (const float*)d_in[9];
    const float* bhh1   = (const float*)d_in[10];
    const float* w2     = (const float*)d_in[11];
    const float* b2     = (const float*)d_in[12];
    float* out = (float*)d_out;

    int Btot = in_sizes[0] / TSTEPS;       // 4096
    int grid = (Btot + NB - 1) / NB;       // 128 CTAs

    cudaFuncSetAttribute(lstm_fused_kernel,
                         cudaFuncAttributeMaxDynamicSharedMemorySize, SMEM_BYTES);
    lstm_fused_kernel<<<grid, NTHREADS, SMEM_BYTES>>>(
        tensor, w1, b1, Wih0, Whh0, bih0, bhh0,
        Wih1, Whh1, bih1, bhh1, w2, b2, out);
}